// round 14
// baseline (speedup 1.0000x reference)
#include <cuda_runtime.h>

#define BB 8
#define LL 512
#define DD 128
#define INV_SCALE 0.08838834764831843f   // 1/sqrt(128)

typedef unsigned long long ull;

// ---- scratch (no cudaMalloc allowed) ----
__device__ float g_EQ[BB*LL*DD];   // exp(2*Qproj)
__device__ float g_EK[BB*LL*DD];   // exp(2*Kproj)
__device__ float g_V [BB*LL*DD];

__device__ __forceinline__ float frcp(float x) {
    float y;
    asm("rcp.approx.f32 %0, %1;" : "=f"(y) : "f"(x));
    return y;
}
__device__ __forceinline__ ull ffma2(ull a, ull b, ull c) {
    ull d;
    asm("fma.rn.f32x2 %0, %1, %2, %3;" : "=l"(d) : "l"(a), "l"(b), "l"(c));
    return d;
}
__device__ __forceinline__ ull fmul2(ull a, ull b) {
    ull d;
    asm("mul.rn.f32x2 %0, %1, %2;" : "=l"(d) : "l"(a), "l"(b));
    return d;
}
__device__ __forceinline__ ull fadd2(ull a, ull b) {
    ull d;
    asm("add.rn.f32x2 %0, %1, %2;" : "=l"(d) : "l"(a), "l"(b));
    return d;
}
__device__ __forceinline__ ull pack2(float x) {
    ull d;
    asm("mov.b64 %0, {%1, %1};" : "=l"(d) : "f"(x));
    return d;
}
__device__ __forceinline__ ull pack2two(float x, float y) {
    ull d;
    asm("mov.b64 %0, {%1, %2};" : "=l"(d) : "f"(x), "f"(y));
    return d;
}
__device__ __forceinline__ float2 unpack2(ull v) {
    float2 r;
    asm("mov.b64 {%0, %1}, %2;" : "=f"(r.x), "=f"(r.y) : "l"(v));
    return r;
}

// =====================================================================
// Projection (96 blocks, 128x128 tiles, 256 thr, 8x8 tile, FFMA2).
// Epilogue: exp(2x) for Q,K; identity for V.
// Wt staging remapped lane=r -> conflict-free STS.
// =====================================================================
#define XS_PITCH 129
#define WT_PITCH 130
#define PROJ_SMEM_FLOATS (128*XS_PITCH + 128*WT_PITCH)

__global__ void __launch_bounds__(256) proj_kernel(
    const float* __restrict__ Xq, const float* __restrict__ Xk, const float* __restrict__ Xv,
    const float* __restrict__ Wq, const float* __restrict__ bq,
    const float* __restrict__ Wk, const float* __restrict__ bk,
    const float* __restrict__ Wv, const float* __restrict__ bv)
{
    extern __shared__ float sm[];
    float* Xs = sm;                    // [128][129]
    float* Wt = sm + 128*XS_PITCH;     // [128][130]  Wt[d][c]
    __shared__ float bs[DD];

    int bx  = blockIdx.x;
    int mat = bx >> 5;
    int rt  = bx & 31;
    const float *X, *W, *bias;
    float* out;
    if (mat == 0)      { X = Xq; W = Wq; bias = bq; out = g_EQ; }
    else if (mat == 1) { X = Xk; W = Wk; bias = bk; out = g_EK; }
    else               { X = Xv; W = Wv; bias = bv; out = g_V;  }

    int tid = threadIdx.x;
    const float4* Xg = (const float4*)(X + rt*128*DD);
    const float4* Wg = (const float4*)W;
    #pragma unroll
    for (int it = 0; it < 16; ++it) {
        int idx = it*256 + tid;           // 0..4095
        // X: coalesced LDG, contiguous STS (lane = d4)
        {
            int d4  = idx & 31;
            int r   = idx >> 5;
            float4 xv = Xg[idx];
            float* xd = Xs + r*XS_PITCH + 4*d4;
            xd[0] = xv.x; xd[1] = xv.y; xd[2] = xv.z; xd[3] = xv.w;
        }
        // W: lane = r-low -> conflict-free transposed STS (scattered LDG, L2-resident)
        {
            int rlo = idx & 31;
            int hi  = idx >> 5;            // 0..127
            int d4  = hi & 31;
            int r   = ((hi >> 5) << 5) + rlo;   // 0..127, lane-stride 1
            float4 wv = Wg[r*32 + d4];
            Wt[(4*d4+0)*WT_PITCH + r] = wv.x;
            Wt[(4*d4+1)*WT_PITCH + r] = wv.y;
            Wt[(4*d4+2)*WT_PITCH + r] = wv.z;
            Wt[(4*d4+3)*WT_PITCH + r] = wv.w;
        }
    }
    if (tid < DD) bs[tid] = bias[tid];
    __syncthreads();

    int tr = tid >> 4;     // 0..15 (8-row group)
    int tc = tid & 15;     // 0..15 (8-col group)
    const float* xb = Xs + (tr*8)*XS_PITCH;
    const float* wb = Wt + tc*8;

    ull acc[8][4];
    #pragma unroll
    for (int i = 0; i < 8; ++i)
        #pragma unroll
        for (int j = 0; j < 4; ++j) acc[i][j] = 0ull;

    #pragma unroll 4
    for (int d = 0; d < DD; ++d) {
        float xs[8]; ull xp[8]; ull wp[4];
        #pragma unroll
        for (int i = 0; i < 8; ++i) xs[i] = xb[i*XS_PITCH + d];
        #pragma unroll
        for (int j = 0; j < 4; ++j) wp[j] = *(const ull*)(wb + d*WT_PITCH + 2*j);
        #pragma unroll
        for (int i = 0; i < 8; ++i) xp[i] = pack2(xs[i]);
        #pragma unroll
        for (int i = 0; i < 8; ++i)
            #pragma unroll
            for (int j = 0; j < 4; ++j) acc[i][j] = ffma2(xp[i], wp[j], acc[i][j]);
    }

    int rbase = rt*128 + tr*8;
    #pragma unroll
    for (int i = 0; i < 8; ++i) {
        float* orow = out + (rbase + i)*DD + tc*8;
        #pragma unroll
        for (int j = 0; j < 4; ++j) {
            float2 v = unpack2(acc[i][j]);
            float o0 = v.x + bs[tc*8 + 2*j+0];
            float o1 = v.y + bs[tc*8 + 2*j+1];
            if (mat != 2) { o0 = __expf(2.0f*o0); o1 = __expf(2.0f*o1); }
            orow[2*j+0] = o0;
            orow[2*j+1] = o1;
        }
    }
}

// =====================================================================
// Attention. Block = (batch b, 32-q tile), 1024 threads, lane = q.
// Phase 1: iw = 1/(-2w); Eq'' = Eq*iw.  D = ffma2(dupEq'', ekpair, dupiw)
//   score(shifted) = sum_d 1/D; per d-quad, per k-pair:
//     N=(D0+D1)*P23+(D2+D3)*P01, Dp=P01*P23, acc += N*rcp(Dp)
//   256-k tiles (2), warp owns k-pairs j=4w..4w+3 -> EQ4+dups amortized
//   over 4 jj chains (2x ILP vs R13).  All staging STS conflict-free.
// Phase 2: warp-per-row softmax.
// Phase 3: O = P @ V, FFMA2; V staged d-major Vp[d][k2] pitch 33.
// smem (floats):
//   S[32][516]            @ 0       16512  (first 128 reused as iw temp)
//   EKa[32][128] ull2     @ 16512   16384  (pairs d0,d1; Vp reuses)
//   EKb[32][128] ull2     @ 32896   16384  (pairs d2,d3)
//   EQ4[32][32]  float4   @ 49280    4096
//   IWa[32] ull2          @ 53376     128
//   IWb[32] ull2          @ 53504     128
//   rinv[32]              @ 53632      32
// =====================================================================
#define S_PITCH 516
#define SM_S    0
#define SM_EKA  16512
#define SM_EKB  32896
#define SM_EQ4  49280
#define SM_IWA  53376
#define SM_IWB  53504
#define SM_RINV 53632
#define ATTN_SMEM_FLOATS 53664    // 214656 B
#define VP_PITCH 33               // ull units, Vp[128][33]

__global__ void __launch_bounds__(1024) attn_kernel(
    const float* __restrict__ wdel, const float* __restrict__ wsig,
    const float* __restrict__ wthe, float* __restrict__ out)
{
    extern __shared__ float sm[];
    float*      S    = sm + SM_S;
    ulonglong2* EKa  = (ulonglong2*)(sm + SM_EKA);   // [32][128]
    ulonglong2* EKb  = (ulonglong2*)(sm + SM_EKB);   // [32][128]
    float4*     EQ4  = (float4*)(sm + SM_EQ4);       // [d4][q]
    ulonglong2* IWa  = (ulonglong2*)(sm + SM_IWA);
    ulonglong2* IWb  = (ulonglong2*)(sm + SM_IWB);
    float*      rinv = sm + SM_RINV;
    float*      iw   = sm + SM_S;                    // temp during init

    int tid  = threadIdx.x;
    int w    = tid >> 5;
    int lane = tid & 31;
    int b    = blockIdx.x >> 4;
    int qt   = blockIdx.x & 15;
    int qbase = qt * 32;

    const float* EQg = g_EQ + (b*LL + qbase)*DD;
    const float* EKg = g_EK + b*LL*DD;
    const float* Vg  = g_V  + b*LL*DD;

    // ---- init: iw = 1/(-2*w_all) ----
    if (tid < DD) {
        float wv = INV_SCALE + wdel[tid] + wsig[tid] + wthe[tid];
        iw[tid] = 1.0f / (-2.0f * wv);
    }
    __syncthreads();

    // ---- tables: EQ4[d4][q] = Eq*iw (folded), IW dup tables ----
    {
        int q  = tid & 31;
        int d4 = tid >> 5;
        float4 e = ((const float4*)EQg)[q*32 + d4];
        e.x *= iw[4*d4+0]; e.y *= iw[4*d4+1];
        e.z *= iw[4*d4+2]; e.w *= iw[4*d4+3];
        EQ4[d4*32 + q] = e;
    }
    if (tid < 32) {
        ulonglong2 ua; ua.x = pack2(iw[4*tid+0]); ua.y = pack2(iw[4*tid+1]);
        ulonglong2 ub; ub.x = pack2(iw[4*tid+2]); ub.y = pack2(iw[4*tid+3]);
        IWa[tid] = ua; IWb[tid] = ub;
    }
    // ordered by first kt-loop __syncthreads

    // ---------------- Phase 1: scores (2 tiles of 256 k) ----------------
    int j0 = 4*w;                 // this warp's k-pair indices j0..j0+3

    for (int kt = 0; kt < 2; ++kt) {
        __syncthreads();   // EK region free (covers table init on kt=0)
        {   // stage 256-k tile; lane = j-low -> conflict-free STS
            const float4* EK4g = (const float4*)(EKg + kt*256*DD);
            #pragma unroll
            for (int it = 0; it < 4; ++it) {
                int cidx = it*1024 + tid;      // 0..4095
                int j  = cidx & 127;           // lane-stride 1
                int d4 = cidx >> 7;            // 0..31
                float4 a  = EK4g[(2*j)*32 + d4];
                float4 bb = EK4g[(2*j+1)*32 + d4];
                ulonglong2 ua; ua.x = pack2two(a.x, bb.x); ua.y = pack2two(a.y, bb.y);
                ulonglong2 ub; ub.x = pack2two(a.z, bb.z); ub.y = pack2two(a.w, bb.w);
                EKa[d4*128 + j] = ua;
                EKb[d4*128 + j] = ub;
            }
        }
        __syncthreads();

        ull acc0 = 0ull, acc1 = 0ull, acc2 = 0ull, acc3 = 0ull;
        #pragma unroll 2
        for (int d4 = 0; d4 < 32; ++d4) {
            float4 eqv = EQ4[d4*32 + lane];
            ull eq0 = pack2(eqv.x), eq1 = pack2(eqv.y);
            ull eq2 = pack2(eqv.z), eq3 = pack2(eqv.w);
            ulonglong2 ia = IWa[d4];
            ulonglong2 ib = IWb[d4];
            const ulonglong2* pka = EKa + d4*128 + j0;
            const ulonglong2* pkb = EKb + d4*128 + j0;
            #pragma unroll
            for (int jj = 0; jj < 4; ++jj) {
                ulonglong2 ka = pka[jj];
                ulonglong2 kb = pkb[jj];
                ull D0 = ffma2(eq0, ka.x, ia.x);
                ull D1 = ffma2(eq1, ka.y, ia.y);
                ull D2 = ffma2(eq2, kb.x, ib.x);
                ull D3 = ffma2(eq3, kb.y, ib.y);
                ull n01 = fadd2(D0, D1);
                ull n23 = fadd2(D2, D3);
                ull P01 = fmul2(D0, D1);
                ull P23 = fmul2(D2, D3);
                ull N   = ffma2(n23, P01, fmul2(n01, P23));
                ull Dp  = fmul2(P01, P23);
                float2 df = unpack2(Dp);
                ull R = pack2two(frcp(df.x), frcp(df.y));
                if      (jj == 0) acc0 = ffma2(N, R, acc0);
                else if (jj == 1) acc1 = ffma2(N, R, acc1);
                else if (jj == 2) acc2 = ffma2(N, R, acc2);
                else              acc3 = ffma2(N, R, acc3);
            }
        }
        float2 s0 = unpack2(acc0);
        float2 s1 = unpack2(acc1);
        float2 s2 = unpack2(acc2);
        float2 s3 = unpack2(acc3);
        float* Sw = S + lane*S_PITCH + kt*256 + 8*w;
        *(float4*)(Sw)     = make_float4(s0.x, s0.y, s1.x, s1.y);
        *(float4*)(Sw + 4) = make_float4(s2.x, s2.y, s3.x, s3.y);
    }
    __syncthreads();   // rows assembled from all 32 warps

    // ---------------- Phase 2: softmax ----------------
    {
        float* Srow = S + w*S_PITCH;
        float v[16];
        float m = -1e30f;
        #pragma unroll
        for (int i = 0; i < 16; ++i) { v[i] = Srow[i*32 + lane]; m = fmaxf(m, v[i]); }
        #pragma unroll
        for (int s = 16; s > 0; s >>= 1) m = fmaxf(m, __shfl_xor_sync(0xffffffffu, m, s));
        float sum = 0.f;
        #pragma unroll
        for (int i = 0; i < 16; ++i) {
            float e = __expf(v[i] - m);
            Srow[i*32 + lane] = e;
            sum += e;
        }
        #pragma unroll
        for (int s = 16; s > 0; s >>= 1) sum += __shfl_xor_sync(0xffffffffu, sum, s);
        if (lane == 0) rinv[w] = 1.0f / sum;
    }

    // ---------------- Phase 3: O = P @ V (FFMA2, V d-major) ----------------
    int r0  = (w & 15) * 2;
    int dh  = w >> 4;
    int dA  = dh*64 + lane;
    ull acc3v[2][2] = {{0,0},{0,0}};
    ull* Vpu = (ull*)(sm + SM_EKA);   // [128][VP_PITCH] : Vp[d][k2]
    const ull* pv0 = Vpu + (size_t)dA*VP_PITCH;
    const ull* pv1 = Vpu + (size_t)(dA+32)*VP_PITCH;

    int sk2 = tid & 31;      // staging: lane = k2 -> conflict-free STS
    int sd4 = tid >> 5;
    const float4* V4g = (const float4*)Vg;

    for (int kt = 0; kt < 8; ++kt) {             // 8 tiles of 64 k
        __syncthreads();   // previous tile consumed (kt=0: softmax done)
        {
            float4 a  = V4g[kt*2048 + (2*sk2)*32 + sd4];
            float4 bb = V4g[kt*2048 + (2*sk2+1)*32 + sd4];
            Vpu[(4*sd4+0)*VP_PITCH + sk2] = pack2two(a.x, bb.x);
            Vpu[(4*sd4+1)*VP_PITCH + sk2] = pack2two(a.y, bb.y);
            Vpu[(4*sd4+2)*VP_PITCH + sk2] = pack2two(a.z, bb.z);
            Vpu[(4*sd4+3)*VP_PITCH + sk2] = pack2two(a.w, bb.w);
        }
        __syncthreads();

        const float* Sb = S + kt*64;
        #pragma unroll 4
        for (int k2 = 0; k2 < 32; ++k2) {
            ull p0 = *(const ull*)(Sb + (r0+0)*S_PITCH + 2*k2);
            ull p1 = *(const ull*)(Sb + (r0+1)*S_PITCH + 2*k2);
            ull v0 = pv0[k2];
            ull v1 = pv1[k2];
            acc3v[0][0] = ffma2(p0, v0, acc3v[0][0]);  acc3v[0][1] = ffma2(p0, v1, acc3v[0][1]);
            acc3v[1][0] = ffma2(p1, v0, acc3v[1][0]);  acc3v[1][1] = ffma2(p1, v1, acc3v[1][1]);
        }
    }

    #pragma unroll
    for (int i = 0; i < 2; ++i) {
        float inv = rinv[r0 + i];
        float2 eo = unpack2(acc3v[i][0]);
        float2 e1 = unpack2(acc3v[i][1]);
        float* orow = out + (size_t)(b*LL + qbase + r0 + i)*DD;
        orow[dA]      = (eo.x + eo.y) * inv;
        orow[dA + 32] = (e1.x + e1.y) * inv;
    }
}

// =====================================================================
extern "C" void kernel_launch(void* const* d_in, const int* in_sizes, int n_in,
                              void* d_out, int out_size)
{
    const float* query = (const float*)d_in[0];
    const float* key   = (const float*)d_in[1];
    const float* value = (const float*)d_in[2];
    const float* Wq    = (const float*)d_in[3];
    const float* bq    = (const float*)d_in[4];
    const float* Wk    = (const float*)d_in[5];
    const float* bk    = (const float*)d_in[6];
    const float* Wv    = (const float*)d_in[7];
    const float* bv    = (const float*)d_in[8];
    const float* wdel  = (const float*)d_in[9];
    const float* wsig  = (const float*)d_in[11];
    const float* wthe  = (const float*)d_in[13];
    float* out = (float*)d_out;

    const int PROJ_SMEM = PROJ_SMEM_FLOATS * (int)sizeof(float);   // 132608
    const int ATTN_SMEM = ATTN_SMEM_FLOATS * (int)sizeof(float);   // 214656

    cudaFuncSetAttribute(proj_kernel, cudaFuncAttributeMaxDynamicSharedMemorySize, PROJ_SMEM);
    cudaFuncSetAttribute(attn_kernel, cudaFuncAttributeMaxDynamicSharedMemorySize, ATTN_SMEM);

    proj_kernel<<<96, 256, PROJ_SMEM>>>(query, key, value, Wq, bq, Wk, bk, Wv, bv);
    attn_kernel<<<BB*16, 1024, ATTN_SMEM>>>(wdel, wsig, wthe, out);
}